// round 9
// baseline (speedup 1.0000x reference)
#include <cuda_runtime.h>
#include <cstdint>

#define Bv 256
#define Sv 2048
#define Tv 48

// -------- runtime format flags --------
__device__ int g_tags64;   // tags stored as int64 (JAX x64) vs int32
__device__ int g_mask32;   // mask stored as int32 (0/1 words) vs 1-byte bool

// -------- packed f32x2 helpers (sm_103a) --------
#define FMA2(d,a,b,c) asm("fma.rn.f32x2 %0, %1, %2, %3;" : "=l"(d) : "l"(a), "l"(b), "l"(c))
#define ADD2(d,a,b)   asm("add.rn.f32x2 %0, %1, %2;"     : "=l"(d) : "l"(a), "l"(b))
#define MUL2(d,a,b)   asm("mul.rn.f32x2 %0, %1, %2;"     : "=l"(d) : "l"(a), "l"(b))

static __device__ __forceinline__ unsigned long long pack2(float x, float y){
  unsigned long long r; asm("mov.b64 %0, {%1, %2};" : "=l"(r) : "f"(x), "f"(y)); return r;
}
static __device__ __forceinline__ void unpack2(float& x, float& y, unsigned long long v){
  asm("mov.b64 {%0, %1}, %2;" : "=f"(x), "=f"(y) : "l"(v));
}
static __device__ __forceinline__ float rcp_fast(float x){
  float r; asm("rcp.approx.f32 %0, %1;" : "=f"(r) : "f"(x)); return r;
}
static __device__ __forceinline__ int ld_mask(const void* mp, size_t idx, int m32){
  return m32 ? ((const int*)mp)[idx] : (int)((const unsigned char*)mp)[idx];
}

// Parallel format detection (one warp).
__global__ void __launch_bounds__(32) detect_fmt_kernel(
    const unsigned int* __restrict__ tw, const unsigned int* __restrict__ mw){
  const int L = threadIdx.x;
  unsigned int bad64 = 0, badm = 0;
  #pragma unroll
  for (int i = 1 + 2 * L; i < 256; i += 64) bad64 |= (tw[i] != 0u);
  #pragma unroll
  for (int i = L; i < 512; i += 32)         badm  |= (mw[i] > 1u);
  bad64 = __any_sync(0xffffffffu, bad64);
  badm  = __any_sync(0xffffffffu, badm);
  if (L == 0){ g_tags64 = !bad64; g_mask32 = !badm; }
}

// ==== combined kernel, 4 warps; SMSP-steered ====
// Forward warp = (b>>2)&3, score warp = forward^2; other warps exit at once.
// Co-resident CTAs are (b, b+148) [classic placement, 148%4==0], and
// ((b+148)>>2)&3 = ((b>>2)+37)&3 != (b>>2)&3, so the two forward warps always
// land on DIFFERENT SMSPs — this removes the scheduler contention that bound
// round 6 (both CTAs' warp 0 piling on SMSP 0).
__global__ void __launch_bounds__(128, 2) crf_fused_kernel(
    const float* __restrict__ em_all,
    const void* __restrict__ tagsv,
    const void* __restrict__ maskp,
    const float* __restrict__ trans,
    const float* __restrict__ startv,
    const float* __restrict__ endv,
    float* __restrict__ out)
{
  const int b = blockIdx.x;
  const int wid = threadIdx.x >> 5;
  const int L = threadIdx.x & 31;
  const int fwid = (b >> 2) & 3;
  const int swid = fwid ^ 2;
  const int m32 = g_mask32;
  const float* em = em_all + (size_t)b * (Sv * Tv);
  const size_t mbase = (size_t)b * Sv;

  __shared__ float4 pdup[2][24];   // pdup[buf][L] = {p_{2L}, p_{2L}, p_{2L+1}, p_{2L+1}}
  __shared__ float s_score;
  __shared__ double s_norm;

  if (wid != fwid && wid != swid) return;   // exited threads release barriers (sm_70+)

  if (wid == swid){
    // ---------------- score warp: gold-path score ----------------
    const long long* t64 = (const long long*)tagsv;
    const int*       t32 = (const int*)tagsv;
    const int is64 = g_tags64;

    float acc = 0.f;
    int cnt = 0;
    #pragma unroll 4
    for (int s = L; s < Sv; s += 32){
      int ts = is64 ? (int)t64[mbase + s] : t32[mbase + s];
      int m  = ld_mask(maskp, mbase + s, m32);
      cnt += m;
      if (s > 0 && m){
        int tp = is64 ? (int)t64[mbase + s - 1] : t32[mbase + s - 1];
        acc += trans[tp * Tv + ts] + em[s * Tv + ts];
      }
    }
    #pragma unroll
    for (int o = 16; o; o >>= 1){
      acc += __shfl_xor_sync(0xffffffffu, acc, o);
      cnt += __shfl_xor_sync(0xffffffffu, cnt, o);
    }
    if (L == 0){
      int tg0 = is64 ? (int)t64[mbase] : t32[mbase];
      float sc = startv[tg0] + em[tg0] + acc;
      int last = cnt - 1;
      int tl = is64 ? (int)t64[mbase + last] : t32[mbase + last];
      sc += endv[tl];
      s_score = -sc;
    }
  } else {
    // ---------------- forward warp: log-partition ----------------
    // Lanes 0..23 own tag pairs (t0=2L, t0+1). Linear-space matvec with packed
    // f32x2 FMAs. Stable skip-and-reset normalization, cadence 4:
    //   norm (s%4==1): p' = (d*rcp(d_0))*exp(em-em_0);  M += em_0 + log(d_0)
    //   else:          p' =  d          *exp(em-em_0);  M += em_0
    const bool act = (L < 24);
    const int t0 = act ? 2 * L : 0;
    const int t1 = t0 + 1;

    // E columns for this lane's two tags: E[j][t] = exp(transitions[j][t])
    unsigned long long ecol[Tv];
    #pragma unroll
    for (int j = 0; j < Tv; ++j){
      float ex = __expf(trans[j * Tv + t0]);
      float ey = __expf(trans[j * Tv + t1]);
      ecol[j] = pack2(ex, ey);
    }

    // init: alpha0 = start + em[0,:]; normalize by alpha0[tag 0]
    float a0 = startv[t0] + em[t0];
    float a1 = startv[t1] + em[t1];
    float aref = __shfl_sync(0xffffffffu, a0, 0);
    float p0 = __expf(a0 - aref);
    float p1 = __expf(a1 - aref);
    double Macc = (double)aref;
    if (act) pdup[0][L] = make_float4(p0, p0, p1, p1);
    __syncwarp();

    // prefetch slots (steps 1..4) — NAMED registers, never array-indexed
    float2 e0 = *(const float2*)(em + 1 * Tv + t0);
    float2 e1 = *(const float2*)(em + 2 * Tv + t0);
    float2 e2 = *(const float2*)(em + 3 * Tv + t0);
    float2 e3 = *(const float2*)(em + 4 * Tv + t0);
    int m0 = ld_mask(maskp, mbase + 1, m32);
    int m1 = ld_mask(maskp, mbase + 2, m32);
    int m2 = ld_mask(maskp, mbase + 3, m32);
    int m3 = ld_mask(maskp, mbase + 4, m32);

    // bootstrap step-1 emission factors: eoff_t = exp(em[1,t] - em[1,0])
    float erefCur = __shfl_sync(0xffffffffu, e0.x, 0);
    unsigned long long eoffCur = pack2(__expf(e0.x - erefCur),
                                       __expf(e0.y - erefCur));
    int buf = 0;

    // eoff for the NEXT step is computed FIRST so shfl+MUFU hide under matvec.
    #define STEP(EK, MK, EN, SCUR, DO_NORM)                                   \
    {                                                                          \
      const int m_ = MK;                                                       \
      int sn_ = (SCUR) + 4; if (sn_ > Sv - 1) sn_ = Sv - 1;                    \
      EK = *(const float2*)(em + (size_t)sn_ * Tv + t0);                       \
      MK = ld_mask(maskp, mbase + sn_, m32);                                   \
      const float2 en_ = EN;                                                   \
      float erefN_ = __shfl_sync(0xffffffffu, en_.x, 0);                       \
      unsigned long long eoffN_ = pack2(__expf(en_.x - erefN_),                \
                                        __expf(en_.y - erefN_));               \
      unsigned long long acc0 = 0ull, acc1 = 0ull, acc2 = 0ull, acc3 = 0ull;   \
      const ulonglong2* pp_ = (const ulonglong2*)&pdup[buf][0];                \
      _Pragma("unroll")                                                        \
      for (int jj = 0; jj < 24; jj += 2){                                      \
        ulonglong2 va = pp_[jj];                                               \
        ulonglong2 vb = pp_[jj + 1];                                           \
        FMA2(acc0, va.x, ecol[2 * jj + 0], acc0);                              \
        FMA2(acc1, va.y, ecol[2 * jj + 1], acc1);                              \
        FMA2(acc2, vb.x, ecol[2 * jj + 2], acc2);                              \
        FMA2(acc3, vb.y, ecol[2 * jj + 3], acc3);                              \
      }                                                                        \
      ADD2(acc0, acc0, acc1);                                                  \
      ADD2(acc2, acc2, acc3);                                                  \
      ADD2(acc0, acc0, acc2);                                                  \
      unsigned long long q_;                                                   \
      MUL2(q_, acc0, eoffCur);                                                 \
      float mupd_ = erefCur;                                                   \
      if (DO_NORM){                                                            \
        float d0lo_, d0hi_; unpack2(d0lo_, d0hi_, acc0);                       \
        float dref_ = __shfl_sync(0xffffffffu, d0lo_, 0);                      \
        float r_ = rcp_fast(dref_);                                            \
        unsigned long long rd_ = pack2(r_, r_);                                \
        MUL2(q_, q_, rd_);                                                     \
        mupd_ += __logf(dref_);                                                \
      }                                                                        \
      float np0_, np1_; unpack2(np0_, np1_, q_);                               \
      if (m_){ p0 = np0_; p1 = np1_; Macc += (double)mupd_; }                  \
      if (act) pdup[buf ^ 1][L] = make_float4(p0, p0, p1, p1);                 \
      buf ^= 1;                                                                \
      eoffCur = eoffN_; erefCur = erefN_;                                      \
      __syncwarp();                                                            \
    }

    // 511 full groups of 4 steps (s = 1..2044), then 3-step tail (2045..2047).
    #pragma unroll 1
    for (int g = 0; g < 511; ++g){
      const int s = 1 + 4 * g;
      STEP(e0, m0, e1, s + 0, true)
      STEP(e1, m1, e2, s + 1, false)
      STEP(e2, m2, e3, s + 2, false)
      STEP(e3, m3, e0, s + 3, false)
    }
    STEP(e0, m0, e1, 2045, true)
    STEP(e1, m1, e2, 2046, false)
    STEP(e2, m2, e3, 2047, false)
    #undef STEP

    // norm = M + log( sum_t p_t * exp(end_t) )
    float w = 0.f;
    if (act) w = p0 * __expf(endv[t0]) + p1 * __expf(endv[t1]);
    #pragma unroll
    for (int o = 16; o; o >>= 1) w += __shfl_xor_sync(0xffffffffu, w, o);
    if (L == 0) s_norm = Macc + (double)__logf(w);
  }

  __syncthreads();
  if (threadIdx.x == (unsigned)(fwid * 32)) out[b] = s_score + (float)s_norm;
}

extern "C" void kernel_launch(void* const* d_in, const int* in_sizes, int n_in,
                              void* d_out, int out_size)
{
  const float* emissions       = (const float*)d_in[0];
  const void* tags             = d_in[1];
  const void* mask             = d_in[2];
  const float* trans           = (const float*)d_in[3];
  const float* startv          = (const float*)d_in[4];
  const float* endv            = (const float*)d_in[5];
  float* out                   = (float*)d_out;

  detect_fmt_kernel<<<1, 32>>>((const unsigned int*)tags, (const unsigned int*)mask);
  crf_fused_kernel<<<Bv, 128>>>(emissions, tags, mask, trans, startv, endv, out);
}

// round 10
// speedup vs baseline: 1.1492x; 1.1492x over previous
#include <cuda_runtime.h>
#include <cstdint>

#define Bv 256
#define Sv 2048
#define Tv 48

// -------- runtime format flags --------
__device__ int g_tags64;   // tags stored as int64 (JAX x64) vs int32
__device__ int g_mask32;   // mask stored as int32 (0/1 words) vs 1-byte bool

// -------- packed f32x2 helpers (sm_103a) --------
#define FMA2(d,a,b,c) asm("fma.rn.f32x2 %0, %1, %2, %3;" : "=l"(d) : "l"(a), "l"(b), "l"(c))
#define ADD2(d,a,b)   asm("add.rn.f32x2 %0, %1, %2;"     : "=l"(d) : "l"(a), "l"(b))
#define MUL2(d,a,b)   asm("mul.rn.f32x2 %0, %1, %2;"     : "=l"(d) : "l"(a), "l"(b))

static __device__ __forceinline__ unsigned long long pack2(float x, float y){
  unsigned long long r; asm("mov.b64 %0, {%1, %2};" : "=l"(r) : "f"(x), "f"(y)); return r;
}
static __device__ __forceinline__ void unpack2(float& x, float& y, unsigned long long v){
  asm("mov.b64 {%0, %1}, %2;" : "=f"(x), "=f"(y) : "l"(v));
}
static __device__ __forceinline__ float rcp_fast(float x){
  float r; asm("rcp.approx.f32 %0, %1;" : "=f"(r) : "f"(x)); return r;
}
static __device__ __forceinline__ int ld_mask(const void* mp, size_t idx, int m32){
  return m32 ? ((const int*)mp)[idx] : (int)((const unsigned char*)mp)[idx];
}

// Parallel format detection (one warp).
__global__ void __launch_bounds__(32) detect_fmt_kernel(
    const unsigned int* __restrict__ tw, const unsigned int* __restrict__ mw){
  const int L = threadIdx.x;
  unsigned int bad64 = 0, badm = 0;
  #pragma unroll
  for (int i = 1 + 2 * L; i < 256; i += 64) bad64 |= (tw[i] != 0u);
  #pragma unroll
  for (int i = L; i < 512; i += 32)         badm  |= (mw[i] > 1u);
  bad64 = __any_sync(0xffffffffu, bad64);
  badm  = __any_sync(0xffffffffu, badm);
  if (L == 0){ g_tags64 = !bad64; g_mask32 = !badm; }
}

// ==== fused kernel: warp 0 = forward recurrence, warp 1 = gold-path score ====
// (R9 SMSP steering reverted — it regressed; latency-bound, not issue-bound.)
//
// Forward: lanes 0..23 own tag pairs. Linear-space matvec in packed f32x2.
// Stable skip-and-reset normalization (cadence 4) with CURRENT-step d_0.
// All normalizer inputs that don't depend on d are PREFETCHED + PRECOOKED:
//   raw slot k (4 deep): e2 = em[s,t0..t0+1], er = em[s,0] (broadcast LDG),
//                        m = mask[s]          — loaded 4 steps ahead.
//   cooked ring (2): eoff = exp(e2 - er), mup = er — cooked at step s for
//                        step s+1 from a slot loaded 3 steps earlier, so the
//                        shfl is GONE and exp latency is fully off-path.
// Step body is branchless: FSEL for masked update, Kahan float for M.
__global__ void __launch_bounds__(64, 1) crf_fused_kernel(
    const float* __restrict__ em_all,
    const void* __restrict__ tagsv,
    const void* __restrict__ maskp,
    const float* __restrict__ trans,
    const float* __restrict__ startv,
    const float* __restrict__ endv,
    float* __restrict__ out)
{
  const int b = blockIdx.x;
  const int tid = threadIdx.x;
  const int m32 = g_mask32;
  const float* em = em_all + (size_t)b * (Sv * Tv);
  const size_t mbase = (size_t)b * Sv;

  __shared__ float4 pdup[2][32];   // padded to 32 so ALL lanes store (no divergence)
  __shared__ float s_score;
  __shared__ float s_norm;

  if (tid >= 32){
    // ---------------- warp 1: gold-path score ----------------
    const int L = tid - 32;
    const long long* t64 = (const long long*)tagsv;
    const int*       t32 = (const int*)tagsv;
    const int is64 = g_tags64;

    float acc = 0.f;
    int cnt = 0;
    #pragma unroll 4
    for (int s = L; s < Sv; s += 32){
      int ts = is64 ? (int)t64[mbase + s] : t32[mbase + s];
      int m  = ld_mask(maskp, mbase + s, m32);
      cnt += m;
      if (s > 0 && m){
        int tp = is64 ? (int)t64[mbase + s - 1] : t32[mbase + s - 1];
        acc += trans[tp * Tv + ts] + em[s * Tv + ts];
      }
    }
    #pragma unroll
    for (int o = 16; o; o >>= 1){
      acc += __shfl_xor_sync(0xffffffffu, acc, o);
      cnt += __shfl_xor_sync(0xffffffffu, cnt, o);
    }
    if (L == 0){
      int tg0 = is64 ? (int)t64[mbase] : t32[mbase];
      float sc = startv[tg0] + em[tg0] + acc;
      int last = cnt - 1;
      int tl = is64 ? (int)t64[mbase + last] : t32[mbase + last];
      sc += endv[tl];
      s_score = -sc;
    }
  } else {
    // ---------------- warp 0: forward log-partition ----------------
    const int L = tid;
    const bool act = (L < 24);
    const int t0 = act ? 2 * L : 0;
    const int t1 = t0 + 1;

    // E columns for this lane's two tags: E[j][t] = exp(transitions[j][t])
    unsigned long long ecol[Tv];
    #pragma unroll
    for (int j = 0; j < Tv; ++j){
      float ex = __expf(trans[j * Tv + t0]);
      float ey = __expf(trans[j * Tv + t1]);
      ecol[j] = pack2(ex, ey);
    }

    // init: alpha0 = start + em[0,:]; normalize by alpha0[tag 0]
    float a0 = startv[t0] + em[t0];
    float a1 = startv[t1] + em[t1];
    float aref = __shfl_sync(0xffffffffu, a0, 0);
    float p0 = __expf(a0 - aref);
    float p1 = __expf(a1 - aref);
    float Macc = aref;   // Kahan float accumulator
    float kc = 0.f;
    pdup[0][L] = make_float4(p0, p0, p1, p1);
    __syncwarp();

    // raw prefetch slots (steps 1..4) — NAMED registers
    float2 e2_0 = *(const float2*)(em + 1 * Tv + t0);
    float2 e2_1 = *(const float2*)(em + 2 * Tv + t0);
    float2 e2_2 = *(const float2*)(em + 3 * Tv + t0);
    float2 e2_3 = *(const float2*)(em + 4 * Tv + t0);
    float er_0 = em[1 * Tv];   // broadcast normalizer em[s,0] (replaces shfl)
    float er_1 = em[2 * Tv];
    float er_2 = em[3 * Tv];
    float er_3 = em[4 * Tv];
    bool m_0 = ld_mask(maskp, mbase + 1, m32) != 0;
    bool m_1 = ld_mask(maskp, mbase + 2, m32) != 0;
    bool m_2 = ld_mask(maskp, mbase + 3, m32) != 0;
    bool m_3 = ld_mask(maskp, mbase + 4, m32) != 0;

    // bootstrap cooked pair X for step 1
    unsigned long long eoffX = pack2(__expf(e2_0.x - er_0), __expf(e2_0.y - er_0));
    float mupX = er_0;
    unsigned long long eoffY = 0ull;
    float mupY = 0.f;
    int buf = 0;

    // STEP at index SCUR:
    //  consumes raw slot K ((SCUR-1)&3: mask) and cooked pair C (SCUR&1),
    //  refills slot K with step SCUR+4,
    //  cooks pair P for step SCUR+1 from slot N (SCUR&3, loaded 3 steps ago).
    #define STEP(E2K, ERK, MK, E2N, ERN, EOC, MUC, EOP, MUP, SCUR, DO_NORM)   \
    {                                                                          \
      const bool m_ = MK;                                                      \
      const unsigned long long eoff_ = EOC;                                    \
      float mupd_ = MUC;                                                       \
      int sn_ = (SCUR) + 4; if (sn_ > Sv - 1) sn_ = Sv - 1;                    \
      E2K = *(const float2*)(em + (size_t)sn_ * Tv + t0);                      \
      ERK = em[(size_t)sn_ * Tv];                                              \
      MK  = ld_mask(maskp, mbase + sn_, m32) != 0;                             \
      EOP = pack2(__expf(E2N.x - ERN), __expf(E2N.y - ERN));                   \
      MUP = ERN;                                                               \
      unsigned long long acc0 = 0ull, acc1 = 0ull, acc2 = 0ull, acc3 = 0ull;   \
      const ulonglong2* pp_ = (const ulonglong2*)&pdup[buf][0];                \
      _Pragma("unroll")                                                        \
      for (int jj = 0; jj < 24; jj += 2){                                      \
        ulonglong2 va = pp_[jj];                                               \
        ulonglong2 vb = pp_[jj + 1];                                           \
        FMA2(acc0, va.x, ecol[2 * jj + 0], acc0);                              \
        FMA2(acc1, va.y, ecol[2 * jj + 1], acc1);                              \
        FMA2(acc2, vb.x, ecol[2 * jj + 2], acc2);                              \
        FMA2(acc3, vb.y, ecol[2 * jj + 3], acc3);                              \
      }                                                                        \
      ADD2(acc0, acc0, acc1);                                                  \
      ADD2(acc2, acc2, acc3);                                                  \
      ADD2(acc0, acc0, acc2);                                                  \
      unsigned long long q_;                                                   \
      MUL2(q_, acc0, eoff_);                                                   \
      if (DO_NORM){                                                            \
        float d0lo_, d0hi_; unpack2(d0lo_, d0hi_, acc0);                       \
        float dref_ = __shfl_sync(0xffffffffu, d0lo_, 0);                      \
        float r_ = rcp_fast(dref_);                                            \
        unsigned long long rd_ = pack2(r_, r_);                                \
        MUL2(q_, q_, rd_);                                                     \
        mupd_ += __logf(dref_);                                                \
      }                                                                        \
      float np0_, np1_; unpack2(np0_, np1_, q_);                               \
      p0 = m_ ? np0_ : p0;                                                     \
      p1 = m_ ? np1_ : p1;                                                     \
      float madd_ = m_ ? mupd_ : 0.f;                                          \
      float y_ = madd_ - kc;                                                   \
      float t_ = Macc + y_;                                                    \
      kc = (t_ - Macc) - y_;                                                   \
      Macc = t_;                                                               \
      pdup[buf ^ 1][L] = make_float4(p0, p0, p1, p1);                          \
      buf ^= 1;                                                                \
      __syncwarp();                                                            \
    }

    // 511 groups of 4 (s = 1..2044); norm on s%4==1. Then 3-step tail.
    #pragma unroll 1
    for (int g = 0; g < 511; ++g){
      const int s = 1 + 4 * g;
      STEP(e2_0, er_0, m_0,  e2_1, er_1,  eoffX, mupX, eoffY, mupY, s + 0, true)
      STEP(e2_1, er_1, m_1,  e2_2, er_2,  eoffY, mupY, eoffX, mupX, s + 1, false)
      STEP(e2_2, er_2, m_2,  e2_3, er_3,  eoffX, mupX, eoffY, mupY, s + 2, false)
      STEP(e2_3, er_3, m_3,  e2_0, er_0,  eoffY, mupY, eoffX, mupX, s + 3, false)
    }
    STEP(e2_0, er_0, m_0,  e2_1, er_1,  eoffX, mupX, eoffY, mupY, 2045, true)
    STEP(e2_1, er_1, m_1,  e2_2, er_2,  eoffY, mupY, eoffX, mupX, 2046, false)
    STEP(e2_2, er_2, m_2,  e2_3, er_3,  eoffX, mupX, eoffY, mupY, 2047, false)
    #undef STEP

    // norm = M + log( sum_t p_t * exp(end_t) )
    float w = 0.f;
    if (act) w = p0 * __expf(endv[t0]) + p1 * __expf(endv[t1]);
    #pragma unroll
    for (int o = 16; o; o >>= 1) w += __shfl_xor_sync(0xffffffffu, w, o);
    if (L == 0) s_norm = (Macc - kc) + __logf(w);
  }

  __syncthreads();
  if (tid == 0) out[b] = s_score + s_norm;
}

extern "C" void kernel_launch(void* const* d_in, const int* in_sizes, int n_in,
                              void* d_out, int out_size)
{
  const float* emissions       = (const float*)d_in[0];
  const void* tags             = d_in[1];
  const void* mask             = d_in[2];
  const float* trans           = (const float*)d_in[3];
  const float* startv          = (const float*)d_in[4];
  const float* endv            = (const float*)d_in[5];
  float* out                   = (float*)d_out;

  detect_fmt_kernel<<<1, 32>>>((const unsigned int*)tags, (const unsigned int*)mask);
  crf_fused_kernel<<<Bv, 64>>>(emissions, tags, mask, trans, startv, endv, out);
}